// round 15
// baseline (speedup 1.0000x reference)
#include <cuda_runtime.h>
#include <cuda_fp16.h>
#include <math.h>
#include <stdint.h>

// Problem: G=1, E=8, C=2048, H=1024, I=4096
#define EXPERTS 8
#define CDIM 2048
#define HDIM 1024
#define IDIM 4096

#define BM 128
#define BN 64
#define BK 64            // fp16 elements per chunk -> 128B rows
#define NTHREADS 256
#define NSTAGES 3

// Rows 128B; 8B pairs XOR-swizzled: pair' = pair ^ ((row&3)<<2)
#define A_STAGE_BYTES (BM * 128)                       // 16384
#define B_STAGE_BYTES (BN * 128)                       // 8192
#define STAGE_BYTES   (A_STAGE_BYTES + B_STAGE_BYTES)  // 24576
#define SMEM_TOTAL    (NSTAGES * STAGE_BYTES)          // 73728 -> 3 CTAs/SM

// K pre-permuted per 16-element group at 4B-unit (half2) level:
// source unit s stored at pos(s) = s<4 ? 2s : 2(s-4)+1.
// -> 8B pair q of a group = units (q, q+4): one LDS.64 = (a0,a2)/(b0,b1).

#define WSCALE 256.0f
#define INV_WSCALE (1.0f / 256.0f)

// Scratch (device globals; allocation APIs forbidden)
__device__ __half g_hidden[(size_t)EXPERTS * CDIM * IDIM]; // 128 MB (perm fp16)
__device__ __half g_xr[(size_t)EXPERTS * CDIM * HDIM];     // 32 MB  (perm fp16)
__device__ __half g_wiT[(size_t)EXPERTS * HDIM * IDIM];    // 64 MB [E][I][H]
__device__ __half g_woT[(size_t)EXPERTS * HDIM * IDIM];    // 64 MB [E][H][I]

__device__ __forceinline__ float gelu_exact(float x) {
    return 0.5f * x * (1.0f + erff(x * 0.70710678118654752440f));
}
__device__ __forceinline__ uint32_t smem_u32(const void* p) {
    uint32_t a;
    asm("{ .reg .u64 t; cvta.to.shared.u64 t, %1; cvt.u32.u64 %0, t; }" : "=r"(a) : "l"(p));
    return a;
}
__device__ __forceinline__ void cp_async16(uint32_t dst, const void* src) {
    asm volatile("cp.async.cg.shared.global [%0], [%1], 16;"
                 :: "r"(dst), "l"(src) : "memory");
}
__device__ __forceinline__ void cp_commit() {
    asm volatile("cp.async.commit_group;" ::: "memory");
}
__device__ __forceinline__ void cp_wait1() {
    asm volatile("cp.async.wait_group 1;" ::: "memory");
}
#define MMA_F16(accv, a0, a1, a2, a3, b0, b1)                                    \
    asm volatile(                                                                \
        "mma.sync.aligned.m16n8k16.row.col.f32.f16.f16.f32 "                     \
        "{%0,%1,%2,%3}, {%4,%5,%6,%7}, {%8,%9}, {%0,%1,%2,%3};\n"                \
        : "+f"((accv)[0]), "+f"((accv)[1]), "+f"((accv)[2]), "+f"((accv)[3])     \
        : "r"(a0), "r"(a1), "r"(a2), "r"(a3), "r"(b0), "r"(b1))

// ---------------- x: fp32 -> fp16, 16-group unit permute ----------------
__global__ void __launch_bounds__(256)
cvt_perm_h(const float* __restrict__ in, __half* __restrict__ out, size_t n16)
{
    size_t j = (size_t)blockIdx.x * 256 + threadIdx.x;
    if (j >= n16) return;
    const float4* ip = reinterpret_cast<const float4*>(in + 16 * j);
    float v[16];
    #pragma unroll
    for (int i = 0; i < 4; ++i) {
        float4 f = ip[i];
        v[4 * i] = f.x; v[4 * i + 1] = f.y; v[4 * i + 2] = f.z; v[4 * i + 3] = f.w;
    }
    __half2 u[8];
    #pragma unroll
    for (int s = 0; s < 8; ++s) {
        const int pos = (s < 4) ? 2 * s : 2 * (s - 4) + 1;
        u[pos] = __halves2half2(__float2half_rn(v[2 * s]), __float2half_rn(v[2 * s + 1]));
    }
    uint4* op = reinterpret_cast<uint4*>(out + 16 * j);
    const uint32_t* ub = reinterpret_cast<const uint32_t*>(u);
    op[0] = make_uint4(ub[0], ub[1], ub[2], ub[3]);
    op[1] = make_uint4(ub[4], ub[5], ub[6], ub[7]);
}

// ------- weights: transpose + fp32->fp16 (xWSCALE) + 16-group unit permute --
__global__ void __launch_bounds__(256)
transpose_cvt_perm_h(const float* __restrict__ in, __half* __restrict__ out,
                     int R, int C)
{
    __shared__ float tile[32][33];
    const int e = blockIdx.z;
    in  += (size_t)e * R * C;
    out += (size_t)e * R * C;
    const int c0 = blockIdx.x * 32;
    const int r0 = blockIdx.y * 32;
    const int tx = threadIdx.x;
    #pragma unroll
    for (int i = threadIdx.y; i < 32; i += 8)
        tile[i][tx] = in[(size_t)(r0 + i) * C + c0 + tx];
    __syncthreads();
    const int p  = tx & 15;
    const int up = p >> 1;
    const int su = (up & 1) ? ((up >> 1) + 4) : (up >> 1);
    const int src = (tx & ~15) | (2 * su + (p & 1));
    #pragma unroll
    for (int i = threadIdx.y; i < 32; i += 8)
        out[(size_t)(c0 + i) * R + r0 + tx] = __float2half_rn(tile[src][i] * WSCALE);
}

// ---------------- pipelined fp16 mma.sync GEMM (perm-K inputs) ---------------
// acc[M,N] = A[M,K] @ BT[N,K]^T per expert (blockIdx.z); B pre-scaled xWSCALE.
// GELU=true : D = __half*, gelu(acc/WSCALE), N-permuted (feeds GEMM2)
// GELU=false: D = float*,  acc/WSCALE
template <bool GELU, int K, int N>
__global__ void __launch_bounds__(NTHREADS, 3)
gemm_f16(const __half* __restrict__ A, const __half* __restrict__ BT, void* Dv)
{
    constexpr int M = CDIM;
    constexpr int nch = K / BK;

    extern __shared__ char smem[];
    const uint32_t sb = smem_u32(smem);

    const int e = blockIdx.z;
    A  += (size_t)e * M * K;
    BT += (size_t)e * N * K;

    const int tid  = threadIdx.x;
    const int lane = tid & 31;
    const int warp = tid >> 5;
    const int m0 = blockIdx.y * BM;
    const int n0 = blockIdx.x * BN;

    // 8 warps: 4 along M (32 rows each), 2 along N (32 cols each)
    const int wm = (warp & 3) * 32;
    const int wn = (warp >> 2) * 32;
    const int q  = lane & 3;
    const int r  = lane >> 2;

    // cp.async: thread covers rows r0g(+32i for A), 16B-quad q4
    const int r0g = tid >> 3;
    const int q4  = tid & 7;
    const int q4s = q4 ^ ((r0g & 3) << 1);
    const char* gA = reinterpret_cast<const char*>(A + (size_t)(m0 + r0g) * K) + q4 * 16;
    const char* gB = reinterpret_cast<const char*>(BT + (size_t)(n0 + r0g) * K) + q4 * 16;
    const uint32_t dstA0 = (uint32_t)(r0g * 128 + q4s * 16);
    const uint32_t dstB0 = dstA0 + A_STAGE_BYTES;   // B rows: r0g 0..63 (i<2)

    // LDS.64 pair offsets per k16 step kk: pair = kk*4+q, swizzled by r&3
    uint32_t pb[4];
    #pragma unroll
    for (int kk = 0; kk < 4; ++kk)
        pb[kk] = (uint32_t)((((kk << 2) | q) ^ ((r & 3) << 2)) << 3);
    const uint32_t arow = (uint32_t)((wm + r) * 128);
    const uint32_t brow = (uint32_t)((wn + r) * 128) + A_STAGE_BYTES;

    float acc[2][4][4];
    #pragma unroll
    for (int i = 0; i < 2; i++)
        #pragma unroll
        for (int j = 0; j < 4; j++) {
            acc[i][j][0] = 0.f; acc[i][j][1] = 0.f;
            acc[i][j][2] = 0.f; acc[i][j][3] = 0.f;
        }

    // prologue: stages 0 and 1
    #pragma unroll
    for (int s = 0; s < 2; ++s) {
        const uint32_t ab = sb + (uint32_t)s * STAGE_BYTES + dstA0;
        const uint32_t bb = sb + (uint32_t)s * STAGE_BYTES + dstB0;
        #pragma unroll
        for (int i = 0; i < 4; ++i)
            cp_async16(ab + i * 4096, gA + (size_t)i * (32 * K * 2));
        #pragma unroll
        for (int i = 0; i < 2; ++i)
            cp_async16(bb + i * 4096, gB + (size_t)i * (32 * K * 2));
        cp_commit();
        gA += BK * 2; gB += BK * 2;
    }

    uint32_t soff_c = 0;
    uint32_t soff_p = 2 * STAGE_BYTES;

    #pragma unroll 1
    for (int t = 0; t < nch; ++t) {
        cp_wait1();
        __syncthreads();

        if (t + 2 < nch) {
            const uint32_t ab = sb + soff_p + dstA0;
            const uint32_t bb = sb + soff_p + dstB0;
            #pragma unroll
            for (int i = 0; i < 4; ++i)
                cp_async16(ab + i * 4096, gA + (size_t)i * (32 * K * 2));
            #pragma unroll
            for (int i = 0; i < 2; ++i)
                cp_async16(bb + i * 4096, gB + (size_t)i * (32 * K * 2));
            gA += BK * 2; gB += BK * 2;
            soff_p = (soff_p == 2 * STAGE_BYTES) ? 0u : soff_p + STAGE_BYTES;
        }
        cp_commit();   // empty group ok — keeps numbering aligned

        const char* Ab = smem + soff_c + arow;
        const char* Bb = smem + soff_c + brow;
        soff_c = (soff_c == 2 * STAGE_BYTES) ? 0u : soff_c + STAGE_BYTES;

        #pragma unroll
        for (int kk = 0; kk < 4; ++kk) {      // 4 k16 steps = k64 chunk
            const char* Ak = Ab + pb[kk];
            const char* Bk = Bb + pb[kk];

            uint2 afl[2], afh[2], bfp[4];
            #pragma unroll
            for (int mf = 0; mf < 2; mf++) {
                afl[mf] = *reinterpret_cast<const uint2*>(Ak + mf * 2048);         // a0,a2
                afh[mf] = *reinterpret_cast<const uint2*>(Ak + mf * 2048 + 1024);  // a1,a3
            }
            #pragma unroll
            for (int nf = 0; nf < 4; nf++)
                bfp[nf] = *reinterpret_cast<const uint2*>(Bk + nf * 1024);         // b0,b1

            #pragma unroll
            for (int mf = 0; mf < 2; mf++)
                #pragma unroll
                for (int nf = 0; nf < 4; nf++)
                    MMA_F16(acc[mf][nf], afl[mf].x, afh[mf].x, afl[mf].y, afh[mf].y,
                            bfp[nf].x, bfp[nf].y);
        }
    }

    // Epilogue
    #pragma unroll
    for (int mf = 0; mf < 2; mf++) {
        #pragma unroll
        for (int nf = 0; nf < 4; nf++) {
            const int row = m0 + wm + mf * 16 + r;
            const int nb  = n0 + wn + nf * 8;
            float v0 = acc[mf][nf][0] * INV_WSCALE;
            float v1 = acc[mf][nf][1] * INV_WSCALE;
            float v2 = acc[mf][nf][2] * INV_WSCALE;
            float v3 = acc[mf][nf][3] * INV_WSCALE;
            if (GELU) {
                __half* Dh = reinterpret_cast<__half*>(Dv) + (size_t)e * M * N;
                v0 = gelu_exact(v0); v1 = gelu_exact(v1);
                v2 = gelu_exact(v2); v3 = gelu_exact(v3);
                const int u   = (nb >> 1) + q;       // half2 unit index
                const int Gu  = u & ~7;
                const int s   = u & 7;
                const int pos = (s < 4) ? 2 * s : 2 * (s - 4) + 1;
                const size_t elem = 2 * (size_t)(Gu + pos);
                *reinterpret_cast<__half2*>(Dh + (size_t)row * N + elem) =
                    __halves2half2(__float2half_rn(v0), __float2half_rn(v1));
                *reinterpret_cast<__half2*>(Dh + (size_t)(row + 8) * N + elem) =
                    __halves2half2(__float2half_rn(v2), __float2half_rn(v3));
            } else {
                float* Df = reinterpret_cast<float*>(Dv) + (size_t)e * M * N;
                const int col = nb + 2 * q;
                *reinterpret_cast<float2*>(&Df[(size_t)row * N + col]) = make_float2(v0, v1);
                *reinterpret_cast<float2*>(&Df[(size_t)(row + 8) * N + col]) = make_float2(v2, v3);
            }
        }
    }
}

// ---------------- launch ----------------
extern "C" void kernel_launch(void* const* d_in, const int* in_sizes, int n_in,
                              void* d_out, int out_size) {
    (void)in_sizes; (void)n_in; (void)out_size;
    const float* x  = (const float*)d_in[0];  // [E][C][H]
    const float* wi = (const float*)d_in[1];  // [E][H][I]
    const float* wo = (const float*)d_in[2];  // [E][I][H]
    float* out = (float*)d_out;               // [E][C][H]

    __half *hidden, *xr, *wiT, *woT;
    cudaGetSymbolAddress((void**)&hidden, g_hidden);
    cudaGetSymbolAddress((void**)&xr, g_xr);
    cudaGetSymbolAddress((void**)&wiT, g_wiT);
    cudaGetSymbolAddress((void**)&woT, g_woT);

    cudaFuncSetAttribute((const void*)gemm_f16<true, HDIM, IDIM>,
                         cudaFuncAttributeMaxDynamicSharedMemorySize, SMEM_TOTAL);
    cudaFuncSetAttribute((const void*)gemm_f16<false, IDIM, HDIM>,
                         cudaFuncAttributeMaxDynamicSharedMemorySize, SMEM_TOTAL);

    // Pre-convert: x -> fp16 perm; weights -> transpose + fp16(xWSCALE) + perm
    const size_t n16 = (size_t)EXPERTS * CDIM * HDIM / 16;
    cvt_perm_h<<<(unsigned)((n16 + 255) / 256), 256>>>(x, xr, n16);
    transpose_cvt_perm_h<<<dim3(IDIM / 32, HDIM / 32, EXPERTS), dim3(32, 8)>>>(wi, wiT, HDIM, IDIM);
    transpose_cvt_perm_h<<<dim3(HDIM / 32, IDIM / 32, EXPERTS), dim3(32, 8)>>>(wo, woT, IDIM, HDIM);

    // GEMM1 + GELU: hidden = gelu(x @ wiT^T)  (hidden fp16, K-permuted)
    gemm_f16<true, HDIM, IDIM><<<dim3(IDIM / BN, CDIM / BM, EXPERTS), NTHREADS, SMEM_TOTAL>>>(
        xr, wiT, (void*)hidden);
    // GEMM2: out = hidden @ woT^T  (fp32 out)
    gemm_f16<false, IDIM, HDIM><<<dim3(HDIM / BN, CDIM / BM, EXPERTS), NTHREADS, SMEM_TOTAL>>>(
        hidden, woT, (void*)out);
}

// round 16
// speedup vs baseline: 1.1868x; 1.1868x over previous
#include <cuda_runtime.h>
#include <cuda_fp16.h>
#include <math.h>
#include <stdint.h>

// Problem: G=1, E=8, C=2048, H=1024, I=4096
#define EXPERTS 8
#define CDIM 2048
#define HDIM 1024
#define IDIM 4096

#define BM 128
#define BN 128
#define BK 64            // fp16 elements per chunk -> 128B rows
#define NTHREADS 256
#define NSTAGES 3

// Rows 128B = 8 x 16B quads; quad swizzle: q' = q ^ (row & 7)
#define A_STAGE_BYTES (BM * 128)                       // 16384
#define B_STAGE_BYTES (BN * 128)                       // 16384
#define STAGE_BYTES   (A_STAGE_BYTES + B_STAGE_BYTES)  // 32768
#define SMEM_TOTAL    (NSTAGES * STAGE_BYTES)          // 98304 -> 2 CTAs/SM

#define WSCALE 256.0f
#define INV_WSCALE (1.0f / 256.0f)

// Scratch (device globals; allocation APIs forbidden)
__device__ __half g_hidden[(size_t)EXPERTS * CDIM * IDIM]; // 128 MB fp16
__device__ __half g_xr[(size_t)EXPERTS * CDIM * HDIM];     // 32 MB  fp16
__device__ __half g_wiT[(size_t)EXPERTS * HDIM * IDIM];    // 64 MB [E][I][H] (x256)
__device__ __half g_woT[(size_t)EXPERTS * HDIM * IDIM];    // 64 MB [E][H][I] (x256)

__device__ __forceinline__ float gelu_exact(float x) {
    return 0.5f * x * (1.0f + erff(x * 0.70710678118654752440f));
}
__device__ __forceinline__ uint32_t smem_u32(const void* p) {
    uint32_t a;
    asm("{ .reg .u64 t; cvta.to.shared.u64 t, %1; cvt.u32.u64 %0, t; }" : "=r"(a) : "l"(p));
    return a;
}
__device__ __forceinline__ void cp_async16(uint32_t dst, const void* src) {
    asm volatile("cp.async.cg.shared.global [%0], [%1], 16;"
                 :: "r"(dst), "l"(src) : "memory");
}
__device__ __forceinline__ void cp_commit() {
    asm volatile("cp.async.commit_group;" ::: "memory");
}
__device__ __forceinline__ void cp_wait1() {
    asm volatile("cp.async.wait_group 1;" ::: "memory");
}
__device__ __forceinline__ void ldsm_x4(uint32_t& r0, uint32_t& r1,
                                        uint32_t& r2, uint32_t& r3, uint32_t addr) {
    asm volatile("ldmatrix.sync.aligned.m8n8.x4.shared.b16 {%0,%1,%2,%3}, [%4];"
                 : "=r"(r0), "=r"(r1), "=r"(r2), "=r"(r3) : "r"(addr));
}
#define MMA_F16(accv, a0, a1, a2, a3, b0, b1)                                    \
    asm volatile(                                                                \
        "mma.sync.aligned.m16n8k16.row.col.f32.f16.f16.f32 "                     \
        "{%0,%1,%2,%3}, {%4,%5,%6,%7}, {%8,%9}, {%0,%1,%2,%3};\n"                \
        : "+f"((accv)[0]), "+f"((accv)[1]), "+f"((accv)[2]), "+f"((accv)[3])     \
        : "r"(a0), "r"(a1), "r"(a2), "r"(a3), "r"(b0), "r"(b1))

// ---------------- x: fp32 -> fp16 (natural order) ----------------
__global__ void __launch_bounds__(256)
cvt_h(const float* __restrict__ in, __half* __restrict__ out, size_t n8)
{
    size_t j = (size_t)blockIdx.x * 256 + threadIdx.x;
    if (j >= n8) return;
    const float4* ip = reinterpret_cast<const float4*>(in + 8 * j);
    float4 f0 = ip[0], f1 = ip[1];
    __half2 u[4];
    u[0] = __halves2half2(__float2half_rn(f0.x), __float2half_rn(f0.y));
    u[1] = __halves2half2(__float2half_rn(f0.z), __float2half_rn(f0.w));
    u[2] = __halves2half2(__float2half_rn(f1.x), __float2half_rn(f1.y));
    u[3] = __halves2half2(__float2half_rn(f1.z), __float2half_rn(f1.w));
    const uint32_t* ub = reinterpret_cast<const uint32_t*>(u);
    *reinterpret_cast<uint4*>(out + 8 * j) = make_uint4(ub[0], ub[1], ub[2], ub[3]);
}

// ------- weights: transpose + fp32->fp16 (xWSCALE), natural order ----------
__global__ void __launch_bounds__(256)
transpose_cvt_h(const float* __restrict__ in, __half* __restrict__ out, int R, int C)
{
    __shared__ float tile[32][33];
    const int e = blockIdx.z;
    in  += (size_t)e * R * C;
    out += (size_t)e * R * C;
    const int c0 = blockIdx.x * 32;
    const int r0 = blockIdx.y * 32;
    const int tx = threadIdx.x;
    #pragma unroll
    for (int i = threadIdx.y; i < 32; i += 8)
        tile[i][tx] = in[(size_t)(r0 + i) * C + c0 + tx];
    __syncthreads();
    #pragma unroll
    for (int i = threadIdx.y; i < 32; i += 8)
        out[(size_t)(c0 + i) * R + r0 + tx] = __float2half_rn(tile[tx][i] * WSCALE);
}

// ---------------- pipelined fp16 mma.sync GEMM (ldmatrix fragments) ----------
// acc[M,N] = A[M,K] @ BT[N,K]^T per expert (blockIdx.z); B pre-scaled xWSCALE.
// GELU=true : D = __half*, gelu(acc/WSCALE) (feeds GEMM2); GELU=false: D = float*
template <bool GELU, int K, int N>
__global__ void __launch_bounds__(NTHREADS, 2)
gemm_f16(const __half* __restrict__ A, const __half* __restrict__ BT, void* Dv)
{
    constexpr int M = CDIM;
    constexpr int nch = K / BK;

    extern __shared__ char smem[];
    const uint32_t sb = smem_u32(smem);

    const int e = blockIdx.z;
    A  += (size_t)e * M * K;
    BT += (size_t)e * N * K;

    const int tid  = threadIdx.x;
    const int lane = tid & 31;
    const int warp = tid >> 5;
    const int m0 = blockIdx.y * BM;
    const int n0 = blockIdx.x * BN;

    // 8 warps: 2 along M (64 rows), 4 along N (32 cols)
    const int wm = (warp & 1) * 64;
    const int wn = (warp >> 1) * 32;
    const int q  = lane & 3;
    const int r  = lane >> 2;

    // cp.async: thread covers rows r0g(+32i), quad q4; store at q4 ^ (row&7)
    const int r0g = tid >> 3;
    const int q4  = tid & 7;
    const int q4s = q4 ^ (r0g & 7);
    const char* gA = reinterpret_cast<const char*>(A + (size_t)(m0 + r0g) * K) + q4 * 16;
    const char* gB = reinterpret_cast<const char*>(BT + (size_t)(n0 + r0g) * K) + q4 * 16;
    const uint32_t dstA0 = (uint32_t)(r0g * 128 + q4s * 16);
    const uint32_t dstB0 = dstA0 + A_STAGE_BYTES;

    // ldmatrix lane roles
    const int jj  = lane >> 3;      // matrix index 0..3
    const int sub = lane & 7;       // row within matrix
    // A x4 (per mf): rows wm+mf*16 + sub + 8*(jj&1), k-half = jj>>1
    const uint32_t rowbA = (uint32_t)((wm + sub + 8 * (jj & 1)) * 128);
    // B x4 (per p): rows wn+16p + sub + 8*(jj>>1), k-half = jj&1
    const uint32_t rowbB = (uint32_t)((wn + sub + 8 * (jj >> 1)) * 128) + A_STAGE_BYTES;
    // per-kk swizzled quad offsets (row&7 == sub for both A and B)
    uint32_t qoffA[4], qoffB[4];
    #pragma unroll
    for (int kk = 0; kk < 4; ++kk) {
        qoffA[kk] = (uint32_t)(((2 * kk + (jj >> 1)) ^ sub) << 4);
        qoffB[kk] = (uint32_t)(((2 * kk + (jj & 1)) ^ sub) << 4);
    }

    float acc[4][4][4];
    #pragma unroll
    for (int i = 0; i < 4; i++)
        #pragma unroll
        for (int j = 0; j < 4; j++) {
            acc[i][j][0] = 0.f; acc[i][j][1] = 0.f;
            acc[i][j][2] = 0.f; acc[i][j][3] = 0.f;
        }

    // prologue: stages 0 and 1
    #pragma unroll
    for (int s = 0; s < 2; ++s) {
        const uint32_t ab = sb + (uint32_t)s * STAGE_BYTES + dstA0;
        const uint32_t bb = sb + (uint32_t)s * STAGE_BYTES + dstB0;
        #pragma unroll
        for (int i = 0; i < 4; ++i)
            cp_async16(ab + i * 4096, gA + (size_t)i * (32 * K * 2));
        #pragma unroll
        for (int i = 0; i < 4; ++i)
            cp_async16(bb + i * 4096, gB + (size_t)i * (32 * K * 2));
        cp_commit();
        gA += BK * 2; gB += BK * 2;
    }

    uint32_t soff_c = 0;
    uint32_t soff_p = 2 * STAGE_BYTES;

    #pragma unroll 1
    for (int t = 0; t < nch; ++t) {
        cp_wait1();
        __syncthreads();

        if (t + 2 < nch) {
            const uint32_t ab = sb + soff_p + dstA0;
            const uint32_t bb = sb + soff_p + dstB0;
            #pragma unroll
            for (int i = 0; i < 4; ++i)
                cp_async16(ab + i * 4096, gA + (size_t)i * (32 * K * 2));
            #pragma unroll
            for (int i = 0; i < 4; ++i)
                cp_async16(bb + i * 4096, gB + (size_t)i * (32 * K * 2));
            gA += BK * 2; gB += BK * 2;
            soff_p = (soff_p == 2 * STAGE_BYTES) ? 0u : soff_p + STAGE_BYTES;
        }
        cp_commit();   // empty group ok — keeps numbering aligned

        const uint32_t Abase = sb + soff_c + rowbA;
        const uint32_t Bbase = sb + soff_c + rowbB;
        soff_c = (soff_c == 2 * STAGE_BYTES) ? 0u : soff_c + STAGE_BYTES;

        #pragma unroll
        for (int kk = 0; kk < 4; ++kk) {      // 4 k16 steps = k64 chunk
            const uint32_t aaddr = Abase + qoffA[kk];
            const uint32_t baddr = Bbase + qoffB[kk];

            uint32_t af[4][4];   // [mf][a0..a3]
            #pragma unroll
            for (int mf = 0; mf < 4; mf++)
                ldsm_x4(af[mf][0], af[mf][1], af[mf][2], af[mf][3],
                        aaddr + mf * 2048);
            uint32_t bf[2][4];   // [p][b0(n lo8), b1(n lo8), b0(n hi8), b1(n hi8)]
            #pragma unroll
            for (int p = 0; p < 2; p++)
                ldsm_x4(bf[p][0], bf[p][1], bf[p][2], bf[p][3],
                        baddr + p * 2048);

            #pragma unroll
            for (int mf = 0; mf < 4; mf++)
                #pragma unroll
                for (int nf = 0; nf < 4; nf++)
                    MMA_F16(acc[mf][nf], af[mf][0], af[mf][1], af[mf][2], af[mf][3],
                            bf[nf >> 1][(nf & 1) * 2], bf[nf >> 1][(nf & 1) * 2 + 1]);
        }
    }

    // Epilogue
    #pragma unroll
    for (int mf = 0; mf < 4; mf++) {
        #pragma unroll
        for (int nf = 0; nf < 4; nf++) {
            const int row = m0 + wm + mf * 16 + r;
            const int col = n0 + wn + nf * 8 + 2 * q;
            float v0 = acc[mf][nf][0] * INV_WSCALE;
            float v1 = acc[mf][nf][1] * INV_WSCALE;
            float v2 = acc[mf][nf][2] * INV_WSCALE;
            float v3 = acc[mf][nf][3] * INV_WSCALE;
            if (GELU) {
                __half* Dh = reinterpret_cast<__half*>(Dv) + (size_t)e * M * N;
                v0 = gelu_exact(v0); v1 = gelu_exact(v1);
                v2 = gelu_exact(v2); v3 = gelu_exact(v3);
                *reinterpret_cast<__half2*>(Dh + (size_t)row * N + col) =
                    __halves2half2(__float2half_rn(v0), __float2half_rn(v1));
                *reinterpret_cast<__half2*>(Dh + (size_t)(row + 8) * N + col) =
                    __halves2half2(__float2half_rn(v2), __float2half_rn(v3));
            } else {
                float* Df = reinterpret_cast<float*>(Dv) + (size_t)e * M * N;
                *reinterpret_cast<float2*>(&Df[(size_t)row * N + col]) = make_float2(v0, v1);
                *reinterpret_cast<float2*>(&Df[(size_t)(row + 8) * N + col]) = make_float2(v2, v3);
            }
        }
    }
}

// ---------------- launch ----------------
extern "C" void kernel_launch(void* const* d_in, const int* in_sizes, int n_in,
                              void* d_out, int out_size) {
    (void)in_sizes; (void)n_in; (void)out_size;
    const float* x  = (const float*)d_in[0];  // [E][C][H]
    const float* wi = (const float*)d_in[1];  // [E][H][I]
    const float* wo = (const float*)d_in[2];  // [E][I][H]
    float* out = (float*)d_out;               // [E][C][H]

    __half *hidden, *xr, *wiT, *woT;
    cudaGetSymbolAddress((void**)&hidden, g_hidden);
    cudaGetSymbolAddress((void**)&xr, g_xr);
    cudaGetSymbolAddress((void**)&wiT, g_wiT);
    cudaGetSymbolAddress((void**)&woT, g_woT);

    cudaFuncSetAttribute((const void*)gemm_f16<true, HDIM, IDIM>,
                         cudaFuncAttributeMaxDynamicSharedMemorySize, SMEM_TOTAL);
    cudaFuncSetAttribute((const void*)gemm_f16<false, IDIM, HDIM>,
                         cudaFuncAttributeMaxDynamicSharedMemorySize, SMEM_TOTAL);

    // Pre-convert: x -> fp16; weights -> transpose + fp16(xWSCALE)
    const size_t n8 = (size_t)EXPERTS * CDIM * HDIM / 8;
    cvt_h<<<(unsigned)((n8 + 255) / 256), 256>>>(x, xr, n8);
    transpose_cvt_h<<<dim3(IDIM / 32, HDIM / 32, EXPERTS), dim3(32, 8)>>>(wi, wiT, HDIM, IDIM);
    transpose_cvt_h<<<dim3(HDIM / 32, IDIM / 32, EXPERTS), dim3(32, 8)>>>(wo, woT, IDIM, HDIM);

    // GEMM1 + GELU: hidden = gelu(x @ wiT^T)  (hidden fp16)
    gemm_f16<true, HDIM, IDIM><<<dim3(IDIM / BN, CDIM / BM, EXPERTS), NTHREADS, SMEM_TOTAL>>>(
        xr, wiT, (void*)hidden);
    // GEMM2: out = hidden @ woT^T  (fp32 out)
    gemm_f16<false, IDIM, HDIM><<<dim3(HDIM / BN, CDIM / BM, EXPERTS), NTHREADS, SMEM_TOTAL>>>(
        hidden, woT, (void*)out);
}